// round 2
// baseline (speedup 1.0000x reference)
#include <cuda_runtime.h>
#include <cstdint>

#define C_CH   256
#define NB     32
#define HH     56
#define WW     56
#define HW     (HH*WW)            // 3136
#define TOTAL  (NB*C_CH*HW)       // 25,690,112 floats
#define SPITCH 60                 // padded smem row pitch (58 cols used)
#define NTHR   196                // 14x14 threads, 4x4 outputs each -> 56x56
#define EPS    1e-5f
#define INVCNT (1.0f/(float)(NB*HW))

// ---- scratch (static device globals; no allocation allowed) ----
__device__ float g_h1[TOTAL];
__device__ float g_h2[TOTAL];
__device__ float g_ps [C_CH*NB];
__device__ float g_ps2[C_CH*NB];
__device__ float g_sc1[C_CH], g_sh1[C_CH];
__device__ float g_sc2[C_CH], g_sh2[C_CH];
__device__ int   g_skip1[C_CH];

// ============================================================
// Direct 3x3 conv, stride 1, pad 1. One block = one (n, channel-pair).
// Each block computes the full 56x56 image for up to 2 output channels,
// looping over input channels with the input tile staged in smem.
// BNIN: apply y = relu(v*scale + shift) to the input while loading
// (fuses BN1+ReLU into conv2's load). skip[] lets conv2 drop input
// channels that are identically zero (mask1==0 && shift1<=0).
// ============================================================
template<bool BNIN, int NC>
__device__ __forceinline__ void conv_body(
    const float* __restrict__ in, const float* __restrict__ wts,
    float* __restrict__ out, int n,
    const int* cidx, const float* mval,
    const float* __restrict__ sc1, const float* __restrict__ sh1,
    const int* __restrict__ skip,
    float* s_in, float* s_w)
{
    const int tid = threadIdx.x;
    // preload all 3x3 weights for the active output channels into smem
    #pragma unroll
    for (int j = 0; j < NC; ++j) {
        const float* wsrc = wts + (size_t)cidx[j] * C_CH * 9;
        for (int i = tid; i < C_CH * 9; i += NTHR) s_w[j * C_CH * 9 + i] = wsrc[i];
    }

    float acc[NC][16];
    #pragma unroll
    for (int j = 0; j < NC; ++j)
        #pragma unroll
        for (int i = 0; i < 16; ++i) acc[j][i] = 0.f;

    const int tx = tid % 14, ty = tid / 14;
    const int x0 = tx * 4, y0 = ty * 4;

    for (int ci = 0; ci < C_CH; ++ci) {
        if (BNIN && skip[ci]) continue;        // uniform across block
        float sc = 1.f, sh = 0.f;
        if (BNIN) { sc = sc1[ci]; sh = sh1[ci]; }
        __syncthreads();                        // protect smem reuse
        const float* gsrc = in + ((size_t)n * C_CH + ci) * HW;
        for (int idx = tid; idx < 58 * 58; idx += NTHR) {
            int y = idx / 58, x = idx - y * 58;
            int gy = y - 1, gx = x - 1;
            float v = 0.f;
            if ((unsigned)gy < (unsigned)HH && (unsigned)gx < (unsigned)WW)
                v = gsrc[gy * WW + gx];
            if (BNIN) v = fmaxf(fmaf(v, sc, sh), 0.f);
            s_in[y * SPITCH + x] = v;
        }
        __syncthreads();

        float wr[NC][9];
        #pragma unroll
        for (int j = 0; j < NC; ++j)
            #pragma unroll
            for (int k = 0; k < 9; ++k) wr[j][k] = s_w[j * C_CH * 9 + ci * 9 + k];

        #pragma unroll
        for (int r = 0; r < 6; ++r) {
            float v[6];
            #pragma unroll
            for (int c = 0; c < 6; ++c) v[c] = s_in[(y0 + r) * SPITCH + x0 + c];
            #pragma unroll
            for (int kh = 0; kh < 3; ++kh) {
                const int hr = r - kh;
                if (hr >= 0 && hr < 4) {
                    #pragma unroll
                    for (int j = 0; j < NC; ++j)
                        #pragma unroll
                        for (int kw = 0; kw < 3; ++kw)
                            #pragma unroll
                            for (int c = 0; c < 4; ++c)
                                acc[j][hr * 4 + c] = fmaf(wr[j][kh * 3 + kw], v[c + kw],
                                                          acc[j][hr * 4 + c]);
                }
            }
        }
    }

    #pragma unroll
    for (int j = 0; j < NC; ++j) {
        const float m = mval[j];
        float* o = out + ((size_t)n * C_CH + cidx[j]) * HW;
        #pragma unroll
        for (int hr = 0; hr < 4; ++hr)
            #pragma unroll
            for (int c = 0; c < 4; ++c)
                o[(y0 + hr) * WW + x0 + c] = acc[j][hr * 4 + c] * m;
    }
}

template<bool BNIN>
__global__ __launch_bounds__(NTHR, 3)
void conv3x3_kernel(const float* __restrict__ in, const float* __restrict__ wts,
                    const float* __restrict__ mask, float* __restrict__ out,
                    const float* __restrict__ sc1, const float* __restrict__ sh1,
                    const int* __restrict__ skip)
{
    __shared__ float s_in[58 * SPITCH];
    __shared__ float s_w[2 * C_CH * 9];

    const int n = blockIdx.x;
    const int c0 = 2 * blockIdx.y, c1 = c0 + 1;
    const float m0 = mask[c0], m1 = mask[c1];
    const int tid = threadIdx.x;

    // masked-out output channels are exactly zero: write zeros (BN reducers read them)
    if (m0 == 0.f) {
        float* o = out + ((size_t)n * C_CH + c0) * HW;
        for (int i = tid; i < HW; i += NTHR) o[i] = 0.f;
    }
    if (m1 == 0.f) {
        float* o = out + ((size_t)n * C_CH + c1) * HW;
        for (int i = tid; i < HW; i += NTHR) o[i] = 0.f;
    }

    int   cidx[2]; float mv[2]; int na = 0;
    if (m0 != 0.f) { cidx[na] = c0; mv[na] = m0; ++na; }
    if (m1 != 0.f) { cidx[na] = c1; mv[na] = m1; ++na; }
    if (na == 0) return;
    if (na == 2)
        conv_body<BNIN, 2>(in, wts, out, n, cidx, mv, sc1, sh1, skip, s_in, s_w);
    else
        conv_body<BNIN, 1>(in, wts, out, n, cidx, mv, sc1, sh1, skip, s_in, s_w);
}

// ============================================================
// BN: deterministic two-stage reduction (no atomics)
// ============================================================
__global__ void bn_partial_kernel(const float* __restrict__ h,
                                  float* __restrict__ ps, float* __restrict__ ps2)
{
    const int c = blockIdx.x, n = blockIdx.y, tid = threadIdx.x;
    const float* src = h + ((size_t)n * C_CH + c) * HW;
    float s = 0.f, s2 = 0.f;
    for (int i = tid; i < HW; i += 256) { float v = src[i]; s += v; s2 = fmaf(v, v, s2); }
    __shared__ float r1[256], r2[256];
    r1[tid] = s; r2[tid] = s2;
    __syncthreads();
    for (int o = 128; o > 0; o >>= 1) {
        if (tid < o) { r1[tid] += r1[tid + o]; r2[tid] += r2[tid + o]; }
        __syncthreads();
    }
    if (tid == 0) { ps[c * NB + n] = r1[0]; ps2[c * NB + n] = r2[0]; }
}

__global__ void bn_finalize_kernel(const float* __restrict__ ps, const float* __restrict__ ps2,
                                   const float* __restrict__ gamma, const float* __restrict__ beta,
                                   const float* __restrict__ mask,
                                   float* __restrict__ sc, float* __restrict__ sh,
                                   int* __restrict__ skip)
{
    const int c = threadIdx.x;   // 256 threads
    float s = 0.f, s2 = 0.f;
    #pragma unroll 8
    for (int nn = 0; nn < NB; ++nn) { s += ps[c * NB + nn]; s2 += ps2[c * NB + nn]; }
    const float mean = s * INVCNT;
    float var = fmaf(-mean, mean, s2 * INVCNT);
    var = fmaxf(var, 0.f);
    const float t = var + EPS;
    float inv = rsqrtf(t);
    inv = inv * (1.5f - 0.5f * t * inv * inv);   // Newton refine (MUFU.RSQ -> ~fp32)
    const float scv = gamma[c] * inv;
    const float shv = fmaf(-mean, scv, beta[c]);
    sc[c] = scv; sh[c] = shv;
    if (skip) skip[c] = (mask[c] == 0.f && shv <= 0.f) ? 1 : 0;
}

// ============================================================
// out = relu( bn2(h2) + x )   (vectorized, 784 float4 per channel-image)
// ============================================================
__global__ void epilogue_kernel(const float* __restrict__ h2, const float* __restrict__ x,
                                const float* __restrict__ sc, const float* __restrict__ sh,
                                float* __restrict__ out, int total4)
{
    int i = blockIdx.x * blockDim.x + threadIdx.x;
    if (i >= total4) return;
    const int c = (i / (HW / 4)) & (C_CH - 1);
    const float s = sc[c], t = sh[c];
    float4 a = reinterpret_cast<const float4*>(h2)[i];
    float4 b = reinterpret_cast<const float4*>(x)[i];
    float4 o;
    o.x = fmaxf(fmaf(a.x, s, t) + b.x, 0.f);
    o.y = fmaxf(fmaf(a.y, s, t) + b.y, 0.f);
    o.z = fmaxf(fmaf(a.z, s, t) + b.z, 0.f);
    o.w = fmaxf(fmaf(a.w, s, t) + b.w, 0.f);
    reinterpret_cast<float4*>(out)[i] = o;
}

// ============================================================
extern "C" void kernel_launch(void* const* d_in, const int* in_sizes, int n_in,
                              void* d_out, int out_size)
{
    const float* x      = (const float*)d_in[0];
    const float* W1     = (const float*)d_in[1];
    const float* W2     = (const float*)d_in[2];
    const float* gamma1 = (const float*)d_in[3];
    const float* beta1  = (const float*)d_in[4];
    const float* gamma2 = (const float*)d_in[5];
    const float* beta2  = (const float*)d_in[6];
    const float* mask1  = (const float*)d_in[7];
    const float* mask2  = (const float*)d_in[8];
    float* out = (float*)d_out;

    float *h1, *h2, *ps, *ps2, *sc1, *sh1, *sc2, *sh2;
    int* skip1;
    cudaGetSymbolAddress((void**)&h1,  g_h1);
    cudaGetSymbolAddress((void**)&h2,  g_h2);
    cudaGetSymbolAddress((void**)&ps,  g_ps);
    cudaGetSymbolAddress((void**)&ps2, g_ps2);
    cudaGetSymbolAddress((void**)&sc1, g_sc1);
    cudaGetSymbolAddress((void**)&sh1, g_sh1);
    cudaGetSymbolAddress((void**)&sc2, g_sc2);
    cudaGetSymbolAddress((void**)&sh2, g_sh2);
    cudaGetSymbolAddress((void**)&skip1, g_skip1);

    dim3 cgrid(NB, C_CH / 2);

    // conv1: h1 = conv(x, W1) * mask1   (masked channels -> zeros, no compute)
    conv3x3_kernel<false><<<cgrid, NTHR>>>(x, W1, mask1, h1, nullptr, nullptr, nullptr);

    // BN1 stats
    bn_partial_kernel<<<dim3(C_CH, NB), 256>>>(h1, ps, ps2);
    bn_finalize_kernel<<<1, C_CH>>>(ps, ps2, gamma1, beta1, mask1, sc1, sh1, skip1);

    // conv2: h2 = conv(relu(bn1(h1)), W2) * mask2 ; BN1+ReLU fused into tile load,
    // identically-zero input channels skipped
    conv3x3_kernel<true><<<cgrid, NTHR>>>(h1, W2, mask2, h2, sc1, sh1, skip1);

    // BN2 stats
    bn_partial_kernel<<<dim3(C_CH, NB), 256>>>(h2, ps, ps2);
    bn_finalize_kernel<<<1, C_CH>>>(ps, ps2, gamma2, beta2, nullptr, sc2, sh2, nullptr);

    // out = relu(bn2(h2) + x)
    const int total4 = TOTAL / 4;
    epilogue_kernel<<<(total4 + 255) / 256, 256>>>(h2, x, sc2, sh2, out, total4);
}

// round 3
// speedup vs baseline: 1.0003x; 1.0003x over previous
#include <cuda_runtime.h>
#include <cstdint>

#define C_CH   256
#define NB     32
#define HH     56
#define WW     56
#define HW     (HH*WW)            // 3136
#define TOTAL  (NB*C_CH*HW)       // 25,690,112 floats
#define SPITCH 60                 // padded smem row pitch (58 cols used)
#define NTHR   196                // 14x14 threads, 4x4 outputs each -> 56x56
#define EPS    1e-5f
#define INVCNT (1.0f/(float)(NB*HW))

// ---- scratch (static device globals; no allocation allowed) ----
__device__ float g_h1[TOTAL];
__device__ float g_h2[TOTAL];
__device__ float g_ps [C_CH*NB];
__device__ float g_ps2[C_CH*NB];
__device__ float g_sc1[C_CH], g_sh1[C_CH];
__device__ float g_sc2[C_CH], g_sh2[C_CH];
__device__ int   g_skip1[C_CH];

// ============================================================
// Direct 3x3 conv, stride 1, pad 1. One block = one (n, channel-pair).
// Each block computes the full 56x56 image for up to 2 output channels,
// looping over input channels with the input tile staged in smem.
// BNIN: apply y = relu(v*scale + shift) to the input while loading
// (fuses BN1+ReLU into conv2's load). skip[] lets conv2 drop input
// channels that are identically zero (mask1==0 && shift1<=0).
// ============================================================
template<bool BNIN, int NC>
__device__ __forceinline__ void conv_body(
    const float* __restrict__ in, const float* __restrict__ wts,
    float* __restrict__ out, int n,
    const int* cidx, const float* mval,
    const float* __restrict__ sc1, const float* __restrict__ sh1,
    const int* __restrict__ skip,
    float* s_in, float* s_w)
{
    const int tid = threadIdx.x;
    // preload all 3x3 weights for the active output channels into smem
    #pragma unroll
    for (int j = 0; j < NC; ++j) {
        const float* wsrc = wts + (size_t)cidx[j] * C_CH * 9;
        for (int i = tid; i < C_CH * 9; i += NTHR) s_w[j * C_CH * 9 + i] = wsrc[i];
    }

    float acc[NC][16];
    #pragma unroll
    for (int j = 0; j < NC; ++j)
        #pragma unroll
        for (int i = 0; i < 16; ++i) acc[j][i] = 0.f;

    const int tx = tid % 14, ty = tid / 14;
    const int x0 = tx * 4, y0 = ty * 4;

    for (int ci = 0; ci < C_CH; ++ci) {
        if (BNIN && skip[ci]) continue;        // uniform across block
        float sc = 1.f, sh = 0.f;
        if (BNIN) { sc = sc1[ci]; sh = sh1[ci]; }
        __syncthreads();                        // protect smem reuse
        const float* gsrc = in + ((size_t)n * C_CH + ci) * HW;
        for (int idx = tid; idx < 58 * 58; idx += NTHR) {
            int y = idx / 58, x = idx - y * 58;
            int gy = y - 1, gx = x - 1;
            float v = 0.f;
            if ((unsigned)gy < (unsigned)HH && (unsigned)gx < (unsigned)WW)
                v = gsrc[gy * WW + gx];
            if (BNIN) v = fmaxf(fmaf(v, sc, sh), 0.f);
            s_in[y * SPITCH + x] = v;
        }
        __syncthreads();

        float wr[NC][9];
        #pragma unroll
        for (int j = 0; j < NC; ++j)
            #pragma unroll
            for (int k = 0; k < 9; ++k) wr[j][k] = s_w[j * C_CH * 9 + ci * 9 + k];

        #pragma unroll
        for (int r = 0; r < 6; ++r) {
            float v[6];
            #pragma unroll
            for (int c = 0; c < 6; ++c) v[c] = s_in[(y0 + r) * SPITCH + x0 + c];
            #pragma unroll
            for (int kh = 0; kh < 3; ++kh) {
                const int hr = r - kh;
                if (hr >= 0 && hr < 4) {
                    #pragma unroll
                    for (int j = 0; j < NC; ++j)
                        #pragma unroll
                        for (int kw = 0; kw < 3; ++kw)
                            #pragma unroll
                            for (int c = 0; c < 4; ++c)
                                acc[j][hr * 4 + c] = fmaf(wr[j][kh * 3 + kw], v[c + kw],
                                                          acc[j][hr * 4 + c]);
                }
            }
        }
    }

    #pragma unroll
    for (int j = 0; j < NC; ++j) {
        const float m = mval[j];
        float* o = out + ((size_t)n * C_CH + cidx[j]) * HW;
        #pragma unroll
        for (int hr = 0; hr < 4; ++hr)
            #pragma unroll
            for (int c = 0; c < 4; ++c)
                o[(y0 + hr) * WW + x0 + c] = acc[j][hr * 4 + c] * m;
    }
}

template<bool BNIN>
__global__ __launch_bounds__(NTHR, 3)
void conv3x3_kernel(const float* __restrict__ in, const float* __restrict__ wts,
                    const float* __restrict__ mask, float* __restrict__ out,
                    const float* __restrict__ sc1, const float* __restrict__ sh1,
                    const int* __restrict__ skip)
{
    __shared__ float s_in[58 * SPITCH];
    __shared__ float s_w[2 * C_CH * 9];

    const int n = blockIdx.x;
    const int c0 = 2 * blockIdx.y, c1 = c0 + 1;
    const float m0 = mask[c0], m1 = mask[c1];
    const int tid = threadIdx.x;

    // masked-out output channels are exactly zero: write zeros (BN reducers read them)
    if (m0 == 0.f) {
        float* o = out + ((size_t)n * C_CH + c0) * HW;
        for (int i = tid; i < HW; i += NTHR) o[i] = 0.f;
    }
    if (m1 == 0.f) {
        float* o = out + ((size_t)n * C_CH + c1) * HW;
        for (int i = tid; i < HW; i += NTHR) o[i] = 0.f;
    }

    int   cidx[2]; float mv[2]; int na = 0;
    if (m0 != 0.f) { cidx[na] = c0; mv[na] = m0; ++na; }
    if (m1 != 0.f) { cidx[na] = c1; mv[na] = m1; ++na; }
    if (na == 0) return;
    if (na == 2)
        conv_body<BNIN, 2>(in, wts, out, n, cidx, mv, sc1, sh1, skip, s_in, s_w);
    else
        conv_body<BNIN, 1>(in, wts, out, n, cidx, mv, sc1, sh1, skip, s_in, s_w);
}

// ============================================================
// BN: deterministic two-stage reduction (no atomics)
// ============================================================
__global__ void bn_partial_kernel(const float* __restrict__ h,
                                  float* __restrict__ ps, float* __restrict__ ps2)
{
    const int c = blockIdx.x, n = blockIdx.y, tid = threadIdx.x;
    const float* src = h + ((size_t)n * C_CH + c) * HW;
    float s = 0.f, s2 = 0.f;
    for (int i = tid; i < HW; i += 256) { float v = src[i]; s += v; s2 = fmaf(v, v, s2); }
    __shared__ float r1[256], r2[256];
    r1[tid] = s; r2[tid] = s2;
    __syncthreads();
    for (int o = 128; o > 0; o >>= 1) {
        if (tid < o) { r1[tid] += r1[tid + o]; r2[tid] += r2[tid + o]; }
        __syncthreads();
    }
    if (tid == 0) { ps[c * NB + n] = r1[0]; ps2[c * NB + n] = r2[0]; }
}

__global__ void bn_finalize_kernel(const float* __restrict__ ps, const float* __restrict__ ps2,
                                   const float* __restrict__ gamma, const float* __restrict__ beta,
                                   const float* __restrict__ mask,
                                   float* __restrict__ sc, float* __restrict__ sh,
                                   int* __restrict__ skip)
{
    const int c = threadIdx.x;   // 256 threads
    float s = 0.f, s2 = 0.f;
    #pragma unroll 8
    for (int nn = 0; nn < NB; ++nn) { s += ps[c * NB + nn]; s2 += ps2[c * NB + nn]; }
    const float mean = s * INVCNT;
    float var = fmaf(-mean, mean, s2 * INVCNT);
    var = fmaxf(var, 0.f);
    const float t = var + EPS;
    float inv = rsqrtf(t);
    inv = inv * (1.5f - 0.5f * t * inv * inv);   // Newton refine (MUFU.RSQ -> ~fp32)
    const float scv = gamma[c] * inv;
    const float shv = fmaf(-mean, scv, beta[c]);
    sc[c] = scv; sh[c] = shv;
    if (skip) skip[c] = (mask[c] == 0.f && shv <= 0.f) ? 1 : 0;
}

// ============================================================
// out = relu( bn2(h2) + x )   (vectorized, 784 float4 per channel-image)
// ============================================================
__global__ void epilogue_kernel(const float* __restrict__ h2, const float* __restrict__ x,
                                const float* __restrict__ sc, const float* __restrict__ sh,
                                float* __restrict__ out, int total4)
{
    int i = blockIdx.x * blockDim.x + threadIdx.x;
    if (i >= total4) return;
    const int c = (i / (HW / 4)) & (C_CH - 1);
    const float s = sc[c], t = sh[c];
    float4 a = reinterpret_cast<const float4*>(h2)[i];
    float4 b = reinterpret_cast<const float4*>(x)[i];
    float4 o;
    o.x = fmaxf(fmaf(a.x, s, t) + b.x, 0.f);
    o.y = fmaxf(fmaf(a.y, s, t) + b.y, 0.f);
    o.z = fmaxf(fmaf(a.z, s, t) + b.z, 0.f);
    o.w = fmaxf(fmaf(a.w, s, t) + b.w, 0.f);
    reinterpret_cast<float4*>(out)[i] = o;
}

// ============================================================
extern "C" void kernel_launch(void* const* d_in, const int* in_sizes, int n_in,
                              void* d_out, int out_size)
{
    const float* x      = (const float*)d_in[0];
    const float* W1     = (const float*)d_in[1];
    const float* W2     = (const float*)d_in[2];
    const float* gamma1 = (const float*)d_in[3];
    const float* beta1  = (const float*)d_in[4];
    const float* gamma2 = (const float*)d_in[5];
    const float* beta2  = (const float*)d_in[6];
    const float* mask1  = (const float*)d_in[7];
    const float* mask2  = (const float*)d_in[8];
    float* out = (float*)d_out;

    float *h1, *h2, *ps, *ps2, *sc1, *sh1, *sc2, *sh2;
    int* skip1;
    cudaGetSymbolAddress((void**)&h1,  g_h1);
    cudaGetSymbolAddress((void**)&h2,  g_h2);
    cudaGetSymbolAddress((void**)&ps,  g_ps);
    cudaGetSymbolAddress((void**)&ps2, g_ps2);
    cudaGetSymbolAddress((void**)&sc1, g_sc1);
    cudaGetSymbolAddress((void**)&sh1, g_sh1);
    cudaGetSymbolAddress((void**)&sc2, g_sc2);
    cudaGetSymbolAddress((void**)&sh2, g_sh2);
    cudaGetSymbolAddress((void**)&skip1, g_skip1);

    dim3 cgrid(NB, C_CH / 2);

    // conv1: h1 = conv(x, W1) * mask1   (masked channels -> zeros, no compute)
    conv3x3_kernel<false><<<cgrid, NTHR>>>(x, W1, mask1, h1, nullptr, nullptr, nullptr);

    // BN1 stats
    bn_partial_kernel<<<dim3(C_CH, NB), 256>>>(h1, ps, ps2);
    bn_finalize_kernel<<<1, C_CH>>>(ps, ps2, gamma1, beta1, mask1, sc1, sh1, skip1);

    // conv2: h2 = conv(relu(bn1(h1)), W2) * mask2 ; BN1+ReLU fused into tile load,
    // identically-zero input channels skipped
    conv3x3_kernel<true><<<cgrid, NTHR>>>(h1, W2, mask2, h2, sc1, sh1, skip1);

    // BN2 stats
    bn_partial_kernel<<<dim3(C_CH, NB), 256>>>(h2, ps, ps2);
    bn_finalize_kernel<<<1, C_CH>>>(ps, ps2, gamma2, beta2, nullptr, sc2, sh2, nullptr);

    // out = relu(bn2(h2) + x)
    const int total4 = TOTAL / 4;
    epilogue_kernel<<<(total4 + 255) / 256, 256>>>(h2, x, sc2, sh2, out, total4);
}

// round 5
// speedup vs baseline: 1.4372x; 1.4368x over previous
#include <cuda_runtime.h>
#include <cstdint>

typedef unsigned long long ull;

#define C_CH   256
#define NB     32
#define HH     56
#define WW     56
#define HW     3136
#define TOTAL  (NB*C_CH*HW)
#define PP     60                 // padded pitch (floats)
#define PR     58                 // padded rows
#define PSZ    (PP*PR)            // 3480 floats per padded channel-image
#define PTOT   (NB*C_CH*PSZ)
#define NTHR   196                // 14x14 threads, 4x4 px each
#define EPS    1e-5f
#define INVCNT (1.0f/(float)(NB*HW))
#define CONV_SMEM (PSZ*4 + 4*C_CH*9*8)   // 13920 + 73728 = 87648 bytes

// ---- scratch ----
__device__ float g_xp [PTOT];    // padded x
__device__ float g_h1 [PTOT];    // padded raw conv1 out (interior valid only)
__device__ float g_h1b[PTOT];    // padded relu(bn1(h1)) incl zero halo
__device__ float g_h2 [TOTAL];   // unpadded conv2 out
__device__ float g_ps [C_CH*NB];
__device__ float g_ps2[C_CH*NB];
__device__ float g_sc1[C_CH], g_sh1[C_CH];
__device__ float g_sc2[C_CH], g_sh2[C_CH];
__device__ int   g_skip1[C_CH];
__device__ int   g_list1[C_CH], g_list2[C_CH];
__device__ int   g_cnt[2];

// ---- f32x2 helpers (Blackwell packed fp32; ptxas never emits from C++) ----
__device__ __forceinline__ void ffma2(ull& d, ull a, ull b) {
    asm("fma.rn.f32x2 %0, %1, %2, %0;" : "+l"(d) : "l"(a), "l"(b));
}
__device__ __forceinline__ ull pk2(float a, float b) {
    ull d; asm("mov.b64 %0, {%1, %2};" : "=l"(d) : "f"(a), "f"(b)); return d;
}
__device__ __forceinline__ float2 upk(ull d) {
    float x, y; asm("mov.b64 {%0, %1}, %2;" : "=f"(x), "=f"(y) : "l"(d));
    return make_float2(x, y);
}

// ============================================================
// compact both masks into active-channel lists (1 block, 512 thr)
// ============================================================
__global__ void compact_kernel(const float* __restrict__ m1, const float* __restrict__ m2,
                               int* __restrict__ l1, int* __restrict__ l2, int* __restrict__ cnt)
{
    int t = threadIdx.x;
    int h = t >> 8, c = t & 255;
    const float* m = h ? m2 : m1;
    int* l = h ? l2 : l1;
    int a = (m[c] != 0.f);
    unsigned b = __ballot_sync(0xffffffffu, a);
    int lane = t & 31, w = t >> 5;
    __shared__ int wc[16];
    if (lane == 0) wc[w] = __popc(b);
    __syncthreads();
    int w0 = h * 8, base = 0;
    for (int i = w0; i < w; ++i) base += wc[i];
    int pre = __popc(b & ((1u << lane) - 1));
    if (a) l[base + pre] = c;
    if (c == 0) { int s = 0; for (int i = w0; i < w0 + 8; ++i) s += wc[i]; cnt[h] = s; }
}

// ============================================================
// x -> padded layout (zero halo)
// ============================================================
__global__ void pad_x_kernel(const float* __restrict__ x, float* __restrict__ xp)
{
    const int c = blockIdx.x, n = blockIdx.y, tid = threadIdx.x;
    const float* src = x + ((size_t)n * C_CH + c) * HW;
    float4* dst = (float4*)(xp + ((size_t)n * C_CH + c) * PSZ);
    for (int j = tid; j < PSZ / 4; j += 256) {
        int row = j / 15, c4 = (j - row * 15) * 4;
        int y = row - 1;
        float4 o;
        float* po = (float*)&o;
        #pragma unroll
        for (int k = 0; k < 4; ++k) {
            int col = c4 + k, xx = col - 1;
            po[k] = ((unsigned)y < (unsigned)HH && (unsigned)xx < (unsigned)WW)
                    ? src[y * WW + xx] : 0.f;
        }
        dst[j] = o;
    }
}

// ============================================================
// h1(pad raw) -> h1b(pad) = relu(bn1(h1)); zero halo; masked channels constant
// ============================================================
__global__ void bnrelu_pad_kernel(const float* __restrict__ h1, float* __restrict__ h1b,
                                  const float* __restrict__ sc, const float* __restrict__ sh,
                                  const float* __restrict__ mask)
{
    const int c = blockIdx.x, n = blockIdx.y, tid = threadIdx.x;
    const size_t base = ((size_t)n * C_CH + c) * PSZ;
    float4* dst = (float4*)(h1b + base);
    const float s = sc[c], t = sh[c];
    if (mask[c] == 0.f) {
        const float cv = fmaxf(t, 0.f);
        for (int j = tid; j < PSZ / 4; j += 256) {
            int row = j / 15, c4 = (j - row * 15) * 4;
            bool ri = (row >= 1 && row <= HH);
            float4 o;
            float* po = (float*)&o;
            #pragma unroll
            for (int k = 0; k < 4; ++k) {
                int col = c4 + k;
                po[k] = (ri && col >= 1 && col <= WW) ? cv : 0.f;
            }
            dst[j] = o;
        }
        return;
    }
    const float4* srcp = (const float4*)(h1 + base);
    for (int j = tid; j < PSZ / 4; j += 256) {
        int row = j / 15, c4 = (j - row * 15) * 4;
        bool ri = (row >= 1 && row <= HH);
        float4 v = srcp[j];
        const float* pv = (const float*)&v;
        float4 o;
        float* po = (float*)&o;
        #pragma unroll
        for (int k = 0; k < 4; ++k) {
            int col = c4 + k;
            po[k] = (ri && col >= 1 && col <= WW)
                    ? fmaxf(fmaf(pv[k], s, t), 0.f) : 0.f;
        }
        dst[j] = o;
    }
}

// ============================================================
// Direct 3x3 conv via packed FFMA2. One block = (n, quad of active out
// channels). Padded input, pure float4 tile staging, weights duplicated
// to f32x2 pairs in smem. BN partial sums fused into the epilogue.
// ============================================================
template<bool SKIP, bool PADOUT>
__global__ __launch_bounds__(NTHR, 2)
void conv_kernel(const float* __restrict__ in, const float* __restrict__ wts,
                 const float* __restrict__ mask,
                 const int* __restrict__ list, const int* __restrict__ cnt, int cntIdx,
                 const int* __restrict__ skip,
                 float* __restrict__ out,
                 float* __restrict__ ps, float* __restrict__ ps2)
{
    extern __shared__ char smem[];
    float* s_in = (float*)smem;                       // 3480 floats
    ull*   s_w2 = (ull*)(smem + PSZ * 4);             // 4*2304 pairs

    const int n = blockIdx.x;
    const int qb = blockIdx.y * 4;
    const int count = cnt[cntIdx];
    if (qb >= count) return;
    const int tid = threadIdx.x;

    int cidx[4]; bool act[4]; float mv[4];
    #pragma unroll
    for (int j = 0; j < 4; ++j) {
        int idx = qb + j;
        act[j] = idx < count;
        cidx[j] = list[act[j] ? idx : (count - 1)];
        mv[j] = mask[cidx[j]];
    }

    // duplicate weights into f32x2 pairs in smem
    #pragma unroll
    for (int j = 0; j < 4; ++j) {
        const float* wsrc = wts + (size_t)cidx[j] * (C_CH * 9);
        for (int i = tid; i < C_CH * 9; i += NTHR) {
            float w = wsrc[i];
            s_w2[j * (C_CH * 9) + i] = pk2(w, w);
        }
    }

    const int tx = tid % 14, ty = tid / 14;
    const int x0 = tx * 4, y0 = ty * 4;

    ull acc[4][4][2];
    #pragma unroll
    for (int j = 0; j < 4; ++j)
        #pragma unroll
        for (int r = 0; r < 4; ++r) { acc[j][r][0] = 0ull; acc[j][r][1] = 0ull; }

    for (int ci = 0; ci < C_CH; ++ci) {
        if (SKIP && skip[ci]) continue;      // uniform across block
        __syncthreads();
        const float4* src = (const float4*)(in + ((size_t)n * C_CH + ci) * PSZ);
        float4* d4 = (float4*)s_in;
        for (int t = tid; t < PSZ / 4; t += NTHR) d4[t] = src[t];
        __syncthreads();

        #pragma unroll
        for (int r = 0; r < 6; ++r) {
            const float* vp = s_in + (y0 + r) * PP + x0;
            float v0 = vp[0], v1 = vp[1], v2 = vp[2], v3 = vp[3], v4 = vp[4], v5 = vp[5];
            ull p01 = pk2(v0, v1), p12 = pk2(v1, v2), p23 = pk2(v2, v3);
            ull p34 = pk2(v3, v4), p45 = pk2(v4, v5);
            #pragma unroll
            for (int kh = 0; kh < 3; ++kh) {
                const int hr = r - kh;
                if (hr < 0 || hr > 3) continue;
                #pragma unroll
                for (int j = 0; j < 4; ++j) {
                    const ull* wj = s_w2 + j * (C_CH * 9) + ci * 9 + kh * 3;
                    ull wa = wj[0], wb = wj[1], wc = wj[2];
                    ffma2(acc[j][hr][0], wa, p01);
                    ffma2(acc[j][hr][1], wa, p23);
                    ffma2(acc[j][hr][0], wb, p12);
                    ffma2(acc[j][hr][1], wb, p34);
                    ffma2(acc[j][hr][0], wc, p23);
                    ffma2(acc[j][hr][1], wc, p45);
                }
            }
        }
    }

    __syncthreads();   // tile smem now reused for BN reduction

    float s[4], s2[4];
    #pragma unroll
    for (int j = 0; j < 4; ++j) {
        s[j] = 0.f; s2[j] = 0.f;
        const float mm = mv[j];
        float* op;
        int opitch;
        if (PADOUT) {
            op = out + ((size_t)n * C_CH + cidx[j]) * PSZ + (y0 + 1) * PP + (x0 + 1);
            opitch = PP;
        } else {
            op = out + ((size_t)n * C_CH + cidx[j]) * HW + y0 * WW + x0;
            opitch = WW;
        }
        #pragma unroll
        for (int hr = 0; hr < 4; ++hr)
            #pragma unroll
            for (int p = 0; p < 2; ++p) {
                float2 f = upk(acc[j][hr][p]);
                float a0 = f.x * mm, a1 = f.y * mm;
                if (act[j]) { op[hr * opitch + 2 * p] = a0; op[hr * opitch + 2 * p + 1] = a1; }
                s[j]  += a0 + a1;
                s2[j] += a0 * a0 + a1 * a1;
            }
    }

    // fused BN partial: deterministic fixed-order block reduce
    #pragma unroll
    for (int j = 0; j < 4; ++j) {
        s_in[j * NTHR + tid] = s[j];
        s_in[(4 + j) * NTHR + tid] = s2[j];
    }
    __syncthreads();
    if (tid < 8) {
        float t = 0.f;
        const float* rp = s_in + tid * NTHR;
        for (int i = 0; i < NTHR; ++i) t += rp[i];
        int j = tid & 3;
        if (act[j]) {
            if (tid < 4) ps[cidx[j] * NB + n] = t;
            else         ps2[cidx[j] * NB + n] = t;
        }
    }
}

// ============================================================
__global__ void bn_finalize_kernel(const float* __restrict__ ps, const float* __restrict__ ps2,
                                   const float* __restrict__ gamma, const float* __restrict__ beta,
                                   const float* __restrict__ mask,
                                   float* __restrict__ sc, float* __restrict__ sh,
                                   int* __restrict__ skip)
{
    const int c = threadIdx.x;
    float s = 0.f, s2 = 0.f;
    if (mask[c] != 0.f) {
        #pragma unroll 8
        for (int nn = 0; nn < NB; ++nn) { s += ps[c * NB + nn]; s2 += ps2[c * NB + nn]; }
    }
    const float mean = s * INVCNT;
    float var = fmaf(-mean, mean, s2 * INVCNT);
    var = fmaxf(var, 0.f);
    const float t = var + EPS;
    float inv = rsqrtf(t);
    inv = inv * (1.5f - 0.5f * t * inv * inv);
    const float scv = gamma[c] * inv;
    const float shv = fmaf(-mean, scv, beta[c]);
    sc[c] = scv; sh[c] = shv;
    if (skip) skip[c] = (mask[c] == 0.f && shv <= 0.f) ? 1 : 0;
}

// ============================================================
// out = relu(bn2(h2) + x); masked2 channels never wrote h2 -> treat as 0
// ============================================================
__global__ void epilogue_kernel(const float* __restrict__ h2, const float* __restrict__ x,
                                const float* __restrict__ sc, const float* __restrict__ sh,
                                const float* __restrict__ mask2,
                                float* __restrict__ out, int total4)
{
    int i = blockIdx.x * blockDim.x + threadIdx.x;
    if (i >= total4) return;
    const int c = (i / (HW / 4)) & (C_CH - 1);
    const float s = sc[c], t = sh[c];
    float4 a;
    if (mask2[c] != 0.f) a = reinterpret_cast<const float4*>(h2)[i];
    else { a.x = a.y = a.z = a.w = 0.f; }
    float4 b = reinterpret_cast<const float4*>(x)[i];
    float4 o;
    o.x = fmaxf(fmaf(a.x, s, t) + b.x, 0.f);
    o.y = fmaxf(fmaf(a.y, s, t) + b.y, 0.f);
    o.z = fmaxf(fmaf(a.z, s, t) + b.z, 0.f);
    o.w = fmaxf(fmaf(a.w, s, t) + b.w, 0.f);
    reinterpret_cast<float4*>(out)[i] = o;
}

// ============================================================
extern "C" void kernel_launch(void* const* d_in, const int* in_sizes, int n_in,
                              void* d_out, int out_size)
{
    const float* x      = (const float*)d_in[0];
    const float* W1     = (const float*)d_in[1];
    const float* W2     = (const float*)d_in[2];
    const float* gamma1 = (const float*)d_in[3];
    const float* beta1  = (const float*)d_in[4];
    const float* gamma2 = (const float*)d_in[5];
    const float* beta2  = (const float*)d_in[6];
    const float* mask1  = (const float*)d_in[7];
    const float* mask2  = (const float*)d_in[8];
    float* out = (float*)d_out;

    float *xp, *h1, *h1b, *h2, *ps, *ps2, *sc1, *sh1, *sc2, *sh2;
    int *skip1, *list1, *list2, *cnt;
    cudaGetSymbolAddress((void**)&xp,   g_xp);
    cudaGetSymbolAddress((void**)&h1,   g_h1);
    cudaGetSymbolAddress((void**)&h1b,  g_h1b);
    cudaGetSymbolAddress((void**)&h2,   g_h2);
    cudaGetSymbolAddress((void**)&ps,   g_ps);
    cudaGetSymbolAddress((void**)&ps2,  g_ps2);
    cudaGetSymbolAddress((void**)&sc1,  g_sc1);
    cudaGetSymbolAddress((void**)&sh1,  g_sh1);
    cudaGetSymbolAddress((void**)&sc2,  g_sc2);
    cudaGetSymbolAddress((void**)&sh2,  g_sh2);
    cudaGetSymbolAddress((void**)&skip1, g_skip1);
    cudaGetSymbolAddress((void**)&list1, g_list1);
    cudaGetSymbolAddress((void**)&list2, g_list2);
    cudaGetSymbolAddress((void**)&cnt,   g_cnt);

    cudaFuncSetAttribute(conv_kernel<false, true>,
                         cudaFuncAttributeMaxDynamicSharedMemorySize, CONV_SMEM);
    cudaFuncSetAttribute(conv_kernel<true, false>,
                         cudaFuncAttributeMaxDynamicSharedMemorySize, CONV_SMEM);

    // 0: active-channel lists
    compact_kernel<<<1, 512>>>(mask1, mask2, list1, list2, cnt);

    // 1: pad x
    pad_x_kernel<<<dim3(C_CH, NB), 256>>>(x, xp);

    // 2: conv1 (padded in -> padded out) + fused BN1 partials
    conv_kernel<false, true><<<dim3(NB, C_CH / 4), NTHR, CONV_SMEM>>>(
        xp, W1, mask1, list1, cnt, 0, nullptr, h1, ps, ps2);

    // 3: BN1 finalize (+ conv2 input-channel skip flags)
    bn_finalize_kernel<<<1, C_CH>>>(ps, ps2, gamma1, beta1, mask1, sc1, sh1, skip1);

    // 4: h1b = relu(bn1(h1)) padded
    bnrelu_pad_kernel<<<dim3(C_CH, NB), 256>>>(h1, h1b, sc1, sh1, mask1);

    // 5: conv2 (skips dead input channels) + fused BN2 partials
    conv_kernel<true, false><<<dim3(NB, C_CH / 4), NTHR, CONV_SMEM>>>(
        h1b, W2, mask2, list2, cnt, 1, skip1, h2, ps, ps2);

    // 6: BN2 finalize
    bn_finalize_kernel<<<1, C_CH>>>(ps, ps2, gamma2, beta2, mask2, sc2, sh2, nullptr);

    // 7: out = relu(bn2(h2) + x)
    const int total4 = TOTAL / 4;
    epilogue_kernel<<<(total4 + 255) / 256, 256>>>(h2, x, sc2, sh2, mask2, out, total4);
}